// round 1
// baseline (speedup 1.0000x reference)
#include <cuda_runtime.h>
#include <math.h>

// Problem dims
#define BB   64
#define TT   256
#define INF  512
#define HIDF 1024
#define OUTF 256
#define NDOM 20

// Scratch for intermediate h = gelu(x@W1 + b1): 64*256*1024 floats = 67 MB
__device__ float g_h[BB * TT * HIDF];
__device__ int   g_dom[BB];

// ---------------------------------------------------------------------------
// Domain decode. hetero_info is declared int64 in the reference, but JAX
// without x64 silently downcasts to int32. Detect which layout we got:
// if int64, the int32 view is [val,0,val,0,...] (values are 0..19 so high
// words are 0). If int32, odd int32 slots hold random 0..19 column-1 values
// (P(all zero) ~= 20^-64 ~= 0). Only touches bytes valid in both layouts.
// ---------------------------------------------------------------------------
__global__ void decode_domains_kernel(const int* __restrict__ hi) {
    __shared__ int s_is64;
    int t = threadIdx.x;
    if (t == 0) s_is64 = 1;
    __syncthreads();
    // check int32 indices 1,3,...,127 (within 512 bytes = min buffer size)
    if (hi[2 * t + 1] != 0) s_is64 = 0;  // benign race: any writer wins
    __syncthreads();
    int is64 = s_is64;
    // int64 layout: element b*2 (column 0) -> int32 index 4*b (low word)
    // int32 layout: element b*2            -> int32 index 2*b
    g_dom[t] = is64 ? hi[4 * t] : hi[2 * t];
}

// ---------------------------------------------------------------------------
// Batched GEMM with per-batch domain-gathered weights.
//   C[b] (TT x NDIM) = A[b] (TT x KDIM) @ W_dom (KDIM x NDIM) + bias_dom
// Optional exact-erf GELU epilogue.
// Tile: 128x128x16, 256 threads, 8x8 per-thread microtile.
// ---------------------------------------------------------------------------
__device__ __forceinline__ float gelu_erf(float v) {
    return 0.5f * v * (1.0f + erff(v * 0.70710678118654752f));
}

template <int KDIM, int NDIM, bool GELU>
__global__ void __launch_bounds__(256, 2)
batched_gemm_kernel(const float* __restrict__ Aall,   // [BB][TT][KDIM]
                    const float* __restrict__ table,  // [NDOM][KDIM*NDIM + NDIM]
                    float* __restrict__ Call)         // [BB][TT][NDIM]
{
    const int b   = blockIdx.z;
    const int dom = g_dom[b];

    const float* A    = Aall + (size_t)b * TT * KDIM;
    const float* W    = table + (size_t)dom * ((size_t)KDIM * NDIM + NDIM);
    const float* bias = W + (size_t)KDIM * NDIM;
    float*       C    = Call + (size_t)b * TT * NDIM;

    const int n0 = blockIdx.x * 128;
    const int m0 = blockIdx.y * 128;

    __shared__ float As[16][128];  // A tile, transposed: As[k][m]
    __shared__ float Ws[16][128];  // W tile:             Ws[k][n]

    const int t  = threadIdx.x;
    const int tx = t & 15;   // col group
    const int ty = t >> 4;   // row group

    float acc[8][8];
#pragma unroll
    for (int i = 0; i < 8; i++)
#pragma unroll
        for (int j = 0; j < 8; j++) acc[i][j] = 0.0f;

    for (int k0 = 0; k0 < KDIM; k0 += 16) {
        __syncthreads();  // prior-iteration reads done before overwrite
        // Load A tile: 128 rows x 16 k. 512 float4 loads, 2 per thread.
        // Store transposed into As[k][m].
#pragma unroll
        for (int it = 0; it < 2; it++) {
            int idx = t + it * 256;
            int row = idx >> 2;        // 0..127
            int c   = idx & 3;         // k-chunk of 4
            float4 v = *reinterpret_cast<const float4*>(
                A + (size_t)(m0 + row) * KDIM + k0 + c * 4);
            As[c * 4 + 0][row] = v.x;
            As[c * 4 + 1][row] = v.y;
            As[c * 4 + 2][row] = v.z;
            As[c * 4 + 3][row] = v.w;
        }
        // Load W tile: 16 k x 128 n. 512 float4 loads, 2 per thread.
#pragma unroll
        for (int it = 0; it < 2; it++) {
            int idx = t + it * 256;
            int k   = idx >> 5;        // 0..15
            int c   = idx & 31;        // n-chunk of 4
            float4 v = *reinterpret_cast<const float4*>(
                W + (size_t)(k0 + k) * NDIM + n0 + c * 4);
            *reinterpret_cast<float4*>(&Ws[k][c * 4]) = v;
        }
        __syncthreads();

#pragma unroll
        for (int k = 0; k < 16; k++) {
            float a[8], w[8];
            float4 a0 = *reinterpret_cast<const float4*>(&As[k][ty * 4]);
            float4 a1 = *reinterpret_cast<const float4*>(&As[k][64 + ty * 4]);
            float4 w0 = *reinterpret_cast<const float4*>(&Ws[k][tx * 4]);
            float4 w1 = *reinterpret_cast<const float4*>(&Ws[k][64 + tx * 4]);
            a[0] = a0.x; a[1] = a0.y; a[2] = a0.z; a[3] = a0.w;
            a[4] = a1.x; a[5] = a1.y; a[6] = a1.z; a[7] = a1.w;
            w[0] = w0.x; w[1] = w0.y; w[2] = w0.z; w[3] = w0.w;
            w[4] = w1.x; w[5] = w1.y; w[6] = w1.z; w[7] = w1.w;
#pragma unroll
            for (int i = 0; i < 8; i++)
#pragma unroll
                for (int j = 0; j < 8; j++)
                    acc[i][j] = fmaf(a[i], w[j], acc[i][j]);
        }
    }

    // Epilogue: bias (+ GELU), vectorized stores.
#pragma unroll
    for (int i = 0; i < 8; i++) {
        int row = m0 + ((i < 4) ? (ty * 4 + i) : (64 + ty * 4 + (i - 4)));
#pragma unroll
        for (int jj = 0; jj < 2; jj++) {
            int col = n0 + ((jj == 0) ? (tx * 4) : (64 + tx * 4));
            float4 r;
            r.x = acc[i][jj * 4 + 0] + bias[col + 0];
            r.y = acc[i][jj * 4 + 1] + bias[col + 1];
            r.z = acc[i][jj * 4 + 2] + bias[col + 2];
            r.w = acc[i][jj * 4 + 3] + bias[col + 3];
            if (GELU) {
                r.x = gelu_erf(r.x);
                r.y = gelu_erf(r.y);
                r.z = gelu_erf(r.z);
                r.w = gelu_erf(r.w);
            }
            *reinterpret_cast<float4*>(C + (size_t)row * NDIM + col) = r;
        }
    }
}

extern "C" void kernel_launch(void* const* d_in, const int* in_sizes, int n_in,
                              void* d_out, int out_size) {
    const float* x   = (const float*)d_in[0];
    const int*   hi  = (const int*)d_in[1];   // int32 or int64 view; decoded on-device
    const float* fc1 = (const float*)d_in[2];
    const float* fc2 = (const float*)d_in[3];
    float*       out = (float*)d_out;

    float* h_ptr = nullptr;
    cudaGetSymbolAddress((void**)&h_ptr, g_h);  // no allocation; graph-safe

    decode_domains_kernel<<<1, 64>>>(hi);

    // GEMM1: h = gelu(x @ W1 + b1), (256 x 512) @ (512 x 1024) per batch
    batched_gemm_kernel<INF, HIDF, true>
        <<<dim3(HIDF / 128, TT / 128, BB), 256>>>(x, fc1, h_ptr);

    // GEMM2: out = h @ W2 + b2, (256 x 1024) @ (1024 x 256) per batch
    batched_gemm_kernel<HIDF, OUTF, false>
        <<<dim3(OUTF / 128, TT / 128, BB), 256>>>(h_ptr, fc2, out);
}

// round 3
// speedup vs baseline: 2.7367x; 2.7367x over previous
#include <cuda_runtime.h>
#include <math.h>
#include <cstdint>

#define BB   64
#define TT   256
#define INF  512
#define HIDF 1024
#define OUTF 256
#define NDOM 20

// Intermediate h = gelu(x@W1+b1), fp32, [B][T][HID]
__device__ float g_h[BB * TT * HIDF];
__device__ int   g_dom[BB];

// ---------------------------------------------------------------------------
__device__ __forceinline__ uint32_t smem_to_u32(const void* p) {
    uint32_t a;
    asm("{ .reg .u64 t; cvta.to.shared.u64 t, %1; cvt.u32.u64 %0, t; }"
        : "=r"(a) : "l"(p));
    return a;
}
__device__ __forceinline__ uint32_t f2tf32(float v) {
    uint32_t u;
    asm("cvt.rna.tf32.f32 %0, %1;" : "=r"(u) : "f"(v));
    return u;
}
#define CP_ASYNC16(dst_u32, src_ptr) \
    asm volatile("cp.async.cg.shared.global [%0], [%1], 16;" \
                 :: "r"(dst_u32), "l"(src_ptr) : "memory")
#define CP_ASYNC_COMMIT() asm volatile("cp.async.commit_group;" ::: "memory")
#define CP_ASYNC_WAIT0()  asm volatile("cp.async.wait_group 0;" ::: "memory")

__device__ __forceinline__ void mma_tf32(float* c, const uint32_t* a, const uint32_t* b) {
    asm volatile(
        "mma.sync.aligned.m16n8k8.row.col.f32.tf32.tf32.f32 "
        "{%0,%1,%2,%3}, {%4,%5,%6,%7}, {%8,%9}, {%0,%1,%2,%3};"
        : "+f"(c[0]), "+f"(c[1]), "+f"(c[2]), "+f"(c[3])
        : "r"(a[0]), "r"(a[1]), "r"(a[2]), "r"(a[3]), "r"(b[0]), "r"(b[1]));
}

__device__ __forceinline__ float gelu_erf(float v) {
    return 0.5f * v * (1.0f + erff(v * 0.70710678118654752f));
}

// ---------------------------------------------------------------------------
// Domain decode (int64-vs-int32 robust)
// ---------------------------------------------------------------------------
__global__ void decode_domains_kernel(const int* __restrict__ hi) {
    __shared__ int s_is64;
    int t = threadIdx.x;
    if (t == 0) s_is64 = 1;
    __syncthreads();
    if (hi[2 * t + 1] != 0) s_is64 = 0;
    __syncthreads();
    g_dom[t] = s_is64 ? hi[4 * t] : hi[2 * t];
}

// ---------------------------------------------------------------------------
// Batched GEMM, mma.sync tf32, C[b] = act[b] @ W_dom (+bias, opt GELU)
// CTA tile 128x128x32, 8 warps (2 M x 4 N), warp tile 64x32.
// Double-buffered cp.async staging.
// ---------------------------------------------------------------------------
#define AST 36    // A smem row stride (floats): conflict-free frag reads
#define BST 136   // B smem row stride (floats)
#define AELEM (128 * AST)
#define BELEM (32 * BST)
#define SMEM_BYTES ((2 * AELEM + 2 * BELEM) * 4)

template <int KDIM, int NDIM, bool GELU>
__global__ void __launch_bounds__(256)
gemm_mma_kernel(const float* __restrict__ Act,    // [BB][TT][KDIM]
                const float* __restrict__ table,  // [NDOM][KDIM*NDIM + NDIM]
                float* __restrict__ Call)         // [BB][TT][NDIM]
{
    extern __shared__ float smem[];
    float* As = smem;                 // [2][AELEM]
    float* Bs = smem + 2 * AELEM;     // [2][BELEM]
    const uint32_t as_u32 = smem_to_u32(As);
    const uint32_t bs_u32 = smem_to_u32(Bs);

    const int t    = threadIdx.x;
    const int lid  = t & 31;
    const int wid  = t >> 5;
    const int wm   = wid & 1;         // 2 warps along M
    const int wn   = wid >> 1;        // 4 warps along N
    const int gid  = lid >> 2;
    const int tid4 = lid & 3;

    const int b  = blockIdx.z;
    const int n0 = blockIdx.x * 128;
    const int m0 = blockIdx.y * 128;
    const int dom = g_dom[b];

    const float* Ag   = Act + (size_t)b * TT * KDIM + (size_t)m0 * KDIM;
    const float* Wg   = table + (size_t)dom * ((size_t)KDIM * NDIM + NDIM);
    const float* bias = Wg + (size_t)KDIM * NDIM;
    float*       C    = Call + (size_t)b * TT * NDIM;

    float acc[4][4][4];
#pragma unroll
    for (int i = 0; i < 4; i++)
#pragma unroll
        for (int j = 0; j < 4; j++)
#pragma unroll
            for (int q = 0; q < 4; q++) acc[i][j][q] = 0.0f;

    constexpr int NKT = KDIM / 32;

    // ---- prologue: stage k-tile 0 into buffer 0
    {
#pragma unroll
        for (int it = 0; it < 4; it++) {
            int c = t + it * 256;
            int ar = c >> 3, akc = c & 7;                 // A: 128 rows x 8 chunks
            CP_ASYNC16(as_u32 + (uint32_t)(ar * AST + akc * 4) * 4,
                       Ag + (size_t)ar * KDIM + akc * 4);
            int br = c >> 5, bnc = c & 31;                // B: 32 rows x 32 chunks
            CP_ASYNC16(bs_u32 + (uint32_t)(br * BST + bnc * 4) * 4,
                       Wg + (size_t)br * NDIM + n0 + bnc * 4);
        }
        CP_ASYNC_COMMIT();
    }

    for (int kt = 0; kt < NKT; kt++) {
        const int p = kt & 1;
        CP_ASYNC_WAIT0();
        __syncthreads();   // tile p ready; all threads done reading buffer p^1

        if (kt + 1 < NKT) {
            const int pn = (kt + 1) & 1;
            const int k0 = (kt + 1) * 32;
#pragma unroll
            for (int it = 0; it < 4; it++) {
                int c = t + it * 256;
                int ar = c >> 3, akc = c & 7;
                CP_ASYNC16(as_u32 + (uint32_t)(pn * AELEM + ar * AST + akc * 4) * 4,
                           Ag + (size_t)ar * KDIM + k0 + akc * 4);
                int br = c >> 5, bnc = c & 31;
                CP_ASYNC16(bs_u32 + (uint32_t)(pn * BELEM + br * BST + bnc * 4) * 4,
                           Wg + (size_t)(k0 + br) * NDIM + n0 + bnc * 4);
            }
            CP_ASYNC_COMMIT();
        }

        const float* Ab = As + p * AELEM;
        const float* Bb = Bs + p * BELEM;
#pragma unroll
        for (int ks = 0; ks < 4; ks++) {
            uint32_t af[4][4];
#pragma unroll
            for (int i = 0; i < 4; i++) {
                int r = wm * 64 + i * 16 + gid;
                int kk = ks * 8 + tid4;
                af[i][0] = f2tf32(Ab[r * AST + kk]);
                af[i][1] = f2tf32(Ab[(r + 8) * AST + kk]);
                af[i][2] = f2tf32(Ab[r * AST + kk + 4]);
                af[i][3] = f2tf32(Ab[(r + 8) * AST + kk + 4]);
            }
            uint32_t bf[4][2];
#pragma unroll
            for (int j = 0; j < 4; j++) {
                int cb = wn * 32 + j * 8 + gid;
                int kk = ks * 8 + tid4;
                bf[j][0] = f2tf32(Bb[kk * BST + cb]);
                bf[j][1] = f2tf32(Bb[(kk + 4) * BST + cb]);
            }
#pragma unroll
            for (int i = 0; i < 4; i++)
#pragma unroll
                for (int j = 0; j < 4; j++)
                    mma_tf32(acc[i][j], af[i], bf[j]);
        }
    }

    // ---- epilogue: bias (+GELU), float2 stores
#pragma unroll
    for (int i = 0; i < 4; i++) {
#pragma unroll
        for (int j = 0; j < 4; j++) {
            int row = m0 + wm * 64 + i * 16 + gid;
            int col = n0 + wn * 32 + j * 8 + tid4 * 2;
            float b0 = __ldg(bias + col), b1 = __ldg(bias + col + 1);
            float2 v;
            v.x = acc[i][j][0] + b0;
            v.y = acc[i][j][1] + b1;
            if (GELU) { v.x = gelu_erf(v.x); v.y = gelu_erf(v.y); }
            *reinterpret_cast<float2*>(C + (size_t)row * NDIM + col) = v;
            v.x = acc[i][j][2] + b0;
            v.y = acc[i][j][3] + b1;
            if (GELU) { v.x = gelu_erf(v.x); v.y = gelu_erf(v.y); }
            *reinterpret_cast<float2*>(C + (size_t)(row + 8) * NDIM + col) = v;
        }
    }
}

extern "C" void kernel_launch(void* const* d_in, const int* in_sizes, int n_in,
                              void* d_out, int out_size) {
    const float* x   = (const float*)d_in[0];
    const int*   hi  = (const int*)d_in[1];
    const float* fc1 = (const float*)d_in[2];
    const float* fc2 = (const float*)d_in[3];
    float*       out = (float*)d_out;

    float* h_ptr = nullptr;
    cudaGetSymbolAddress((void**)&h_ptr, g_h);

    cudaFuncSetAttribute(gemm_mma_kernel<INF, HIDF, true>,
                         cudaFuncAttributeMaxDynamicSharedMemorySize, SMEM_BYTES);
    cudaFuncSetAttribute(gemm_mma_kernel<HIDF, OUTF, false>,
                         cudaFuncAttributeMaxDynamicSharedMemorySize, SMEM_BYTES);

    decode_domains_kernel<<<1, 64>>>(hi);

    // GEMM1: h = gelu(x @ W1 + b1): per-batch (256 x 512) @ (512 x 1024)
    gemm_mma_kernel<INF, HIDF, true>
        <<<dim3(HIDF / 128, TT / 128, BB), 256, SMEM_BYTES>>>(x, fc1, h_ptr);

    // GEMM2: out = h @ W2 + b2: per-batch (256 x 1024) @ (1024 x 256)
    gemm_mma_kernel<HIDF, OUTF, false>
        <<<dim3(OUTF / 128, TT / 128, BB), 256, SMEM_BYTES>>>(h_ptr, fc2, out);
}

// round 4
// speedup vs baseline: 4.1889x; 1.5306x over previous
#include <cuda_runtime.h>
#include <cuda_fp16.h>
#include <math.h>
#include <cstdint>

#define BB   64
#define TT   256
#define INF  512
#define HIDF 1024
#define OUTF 256
#define NDOM 20

#define F1ROW (INF * HIDF + HIDF)     // fp32 table row stride (elements)
#define F2ROW (HIDF * OUTF + OUTF)

// fp16 scratch (converted once per launch by prep kernel)
__device__ __align__(16) __half g_xh[BB * TT * INF];
__device__ __align__(16) __half g_f1h[NDOM * F1ROW];
__device__ __align__(16) __half g_f2h[NDOM * F2ROW];
__device__ __align__(16) __half g_hh[BB * TT * HIDF];   // h = gelu(x@W1+b1)
__device__ int g_dom[BB];

// ---------------------------------------------------------------------------
__device__ __forceinline__ uint32_t smem_to_u32(const void* p) {
    uint32_t a;
    asm("{ .reg .u64 t; cvta.to.shared.u64 t, %1; cvt.u32.u64 %0, t; }"
        : "=r"(a) : "l"(p));
    return a;
}
#define CP_ASYNC16(dst_u32, src_ptr) \
    asm volatile("cp.async.cg.shared.global [%0], [%1], 16;" \
                 :: "r"(dst_u32), "l"(src_ptr) : "memory")
#define CP_ASYNC_COMMIT() asm volatile("cp.async.commit_group;" ::: "memory")
#define CP_ASYNC_WAIT0()  asm volatile("cp.async.wait_group 0;" ::: "memory")

#define LDSM_X4(r0, r1, r2, r3, addr) \
    asm volatile("ldmatrix.sync.aligned.m8n8.x4.shared.b16 {%0,%1,%2,%3}, [%4];" \
                 : "=r"(r0), "=r"(r1), "=r"(r2), "=r"(r3) : "r"(addr))
#define LDSM_X4_T(r0, r1, r2, r3, addr) \
    asm volatile("ldmatrix.sync.aligned.m8n8.x4.trans.shared.b16 {%0,%1,%2,%3}, [%4];" \
                 : "=r"(r0), "=r"(r1), "=r"(r2), "=r"(r3) : "r"(addr))

__device__ __forceinline__ void mma_f16(float* c, const uint32_t* a, const uint32_t* b) {
    asm volatile(
        "mma.sync.aligned.m16n8k16.row.col.f32.f16.f16.f32 "
        "{%0,%1,%2,%3}, {%4,%5,%6,%7}, {%8,%9}, {%0,%1,%2,%3};"
        : "+f"(c[0]), "+f"(c[1]), "+f"(c[2]), "+f"(c[3])
        : "r"(a[0]), "r"(a[1]), "r"(a[2]), "r"(a[3]), "r"(b[0]), "r"(b[1]));
}

__device__ __forceinline__ float gelu_erf(float v) {
    return 0.5f * v * (1.0f + erff(v * 0.70710678118654752f));
}

// ---------------------------------------------------------------------------
// Prep: domain decode (int64-vs-int32 robust) + fp32->fp16 converts
// ---------------------------------------------------------------------------
__device__ __forceinline__ void cvt_range(const float* __restrict__ src,
                                          __half* __restrict__ dst,
                                          int n4, int gtid, int gstride) {
    for (int i = gtid; i < n4; i += gstride) {
        float4 v = *reinterpret_cast<const float4*>(src + (size_t)i * 4);
        __half2 h0 = __floats2half2_rn(v.x, v.y);
        __half2 h1 = __floats2half2_rn(v.z, v.w);
        uint2 pk = make_uint2(*(uint32_t*)&h0, *(uint32_t*)&h1);
        *reinterpret_cast<uint2*>(dst + (size_t)i * 4) = pk;
    }
}

__global__ void prep_kernel(const int* __restrict__ hi,
                            const float* __restrict__ x,
                            const float* __restrict__ fc1,
                            const float* __restrict__ fc2) {
    if (blockIdx.x == 0) {
        __shared__ int s_is64;
        int t = threadIdx.x;
        if (t == 0) s_is64 = 1;
        __syncthreads();
        if (t < 64 && hi[2 * t + 1] != 0) s_is64 = 0;
        __syncthreads();
        if (t < 64) g_dom[t] = s_is64 ? hi[4 * t] : hi[2 * t];
    }
    int gtid = blockIdx.x * blockDim.x + threadIdx.x;
    int gstride = gridDim.x * blockDim.x;
    cvt_range(x,   g_xh,  (BB * TT * INF) / 4, gtid, gstride);
    cvt_range(fc1, g_f1h, (NDOM * F1ROW) / 4,  gtid, gstride);
    cvt_range(fc2, g_f2h, (NDOM * F2ROW) / 4,  gtid, gstride);
}

// ---------------------------------------------------------------------------
// Batched fp16 GEMM: C[b] = act[b] @ W_dom (+fp32 bias, opt GELU)
// CTA tile 128x128x32, 8 warps (2M x 4N), warp tile 64x32, m16n8k16 mma.
// Double-buffered cp.async; ldmatrix fragment loads.
// ---------------------------------------------------------------------------
#define AST 40     // A smem row stride (halfs): banks 20r%32 distinct
#define BST 136    // B smem row stride (halfs): banks 4k%32 distinct
#define AELEM (128 * AST)
#define BELEM (32 * BST)
#define SMEM_BYTES ((2 * AELEM + 2 * BELEM) * 2)

template <int KDIM, int NDIM, int WROW, bool GELU>
__global__ void __launch_bounds__(256, 2)
gemm_f16_kernel(const __half* __restrict__ Act,    // [BB][TT][KDIM] halfs
                const __half* __restrict__ Wtab,   // [NDOM][WROW] halfs (weights at row start)
                const float* __restrict__ Ftab,    // fp32 table (for bias)
                __half* __restrict__ Ch,           // fp16 out (or null)
                float* __restrict__ Cf)            // fp32 out (or null)
{
    extern __shared__ __half smem[];
    __half* As = smem;
    __half* Bs = smem + 2 * AELEM;
    const uint32_t as_u32 = smem_to_u32(As);
    const uint32_t bs_u32 = smem_to_u32(Bs);

    const int t    = threadIdx.x;
    const int lid  = t & 31;
    const int wid  = t >> 5;
    const int wm   = wid & 1;
    const int wn   = wid >> 1;
    const int gid  = lid >> 2;
    const int tid4 = lid & 3;

    const int b   = blockIdx.z;
    const int n0  = blockIdx.x * 128;
    const int m0  = blockIdx.y * 128;
    const int dom = g_dom[b];

    const __half* Ag   = Act + (size_t)b * TT * KDIM + (size_t)m0 * KDIM;
    const __half* Wg   = Wtab + (size_t)dom * WROW;
    const float*  bias = Ftab + (size_t)dom * WROW + (size_t)KDIM * NDIM;

    float acc[4][4][4];
#pragma unroll
    for (int i = 0; i < 4; i++)
#pragma unroll
        for (int j = 0; j < 4; j++)
#pragma unroll
            for (int q = 0; q < 4; q++) acc[i][j][q] = 0.0f;

    constexpr int NKT = KDIM / 32;

    // per-thread ldmatrix source offsets (halfs)
    const int a_row = wm * 64 + (lid & 15);
    const int a_col = (lid >> 4) * 8;
    const int b_krow = lid & 15;
    const int b_ncol0 = wn * 32 + (lid >> 4) * 8;

    // ---- prologue: k-tile 0 -> buffer 0
    {
#pragma unroll
        for (int it = 0; it < 2; it++) {
            int c = t + it * 256;
            int ar = c >> 2, akc = c & 3;               // A: 128 rows x 4 chunks(8h)
            CP_ASYNC16(as_u32 + (uint32_t)(ar * AST + akc * 8) * 2,
                       Ag + (size_t)ar * KDIM + akc * 8);
            int br = c >> 4, bnc = c & 15;              // B: 32 rows x 16 chunks
            CP_ASYNC16(bs_u32 + (uint32_t)(br * BST + bnc * 8) * 2,
                       Wg + (size_t)br * NDIM + n0 + bnc * 8);
        }
        CP_ASYNC_COMMIT();
    }

    for (int kt = 0; kt < NKT; kt++) {
        const int p = kt & 1;
        CP_ASYNC_WAIT0();
        __syncthreads();

        if (kt + 1 < NKT) {
            const int pn = (kt + 1) & 1;
            const int k0 = (kt + 1) * 32;
#pragma unroll
            for (int it = 0; it < 2; it++) {
                int c = t + it * 256;
                int ar = c >> 2, akc = c & 3;
                CP_ASYNC16(as_u32 + (uint32_t)(pn * AELEM + ar * AST + akc * 8) * 2,
                           Ag + (size_t)ar * KDIM + k0 + akc * 8);
                int br = c >> 4, bnc = c & 15;
                CP_ASYNC16(bs_u32 + (uint32_t)(pn * BELEM + br * BST + bnc * 8) * 2,
                           Wg + (size_t)(k0 + br) * NDIM + n0 + bnc * 8);
            }
            CP_ASYNC_COMMIT();
        }

        const uint32_t ab = as_u32 + (uint32_t)(p * AELEM) * 2;
        const uint32_t bb = bs_u32 + (uint32_t)(p * BELEM) * 2;
#pragma unroll
        for (int ks = 0; ks < 2; ks++) {
            uint32_t af[4][4];
#pragma unroll
            for (int i = 0; i < 4; i++) {
                uint32_t addr = ab + (uint32_t)((a_row + i * 16) * AST + ks * 16 + a_col) * 2;
                LDSM_X4(af[i][0], af[i][1], af[i][2], af[i][3], addr);
            }
            uint32_t bf[4][2];
#pragma unroll
            for (int jp = 0; jp < 2; jp++) {
                uint32_t addr = bb + (uint32_t)((ks * 16 + b_krow) * BST + b_ncol0 + jp * 16) * 2;
                LDSM_X4_T(bf[jp * 2][0], bf[jp * 2][1], bf[jp * 2 + 1][0], bf[jp * 2 + 1][1], addr);
            }
#pragma unroll
            for (int i = 0; i < 4; i++)
#pragma unroll
                for (int j = 0; j < 4; j++)
                    mma_f16(acc[i][j], af[i], bf[j]);
        }
    }

    // ---- epilogue: fp32 bias (+GELU); store fp16 or fp32
#pragma unroll
    for (int i = 0; i < 4; i++) {
#pragma unroll
        for (int j = 0; j < 4; j++) {
            int row = m0 + wm * 64 + i * 16 + gid;
            int col = n0 + wn * 32 + j * 8 + tid4 * 2;
            float b0 = __ldg(bias + col), b1 = __ldg(bias + col + 1);
#pragma unroll
            for (int h = 0; h < 2; h++) {
                float vx = acc[i][j][h * 2 + 0] + b0;
                float vy = acc[i][j][h * 2 + 1] + b1;
                if (GELU) { vx = gelu_erf(vx); vy = gelu_erf(vy); }
                size_t off = (size_t)b * TT * NDIM + (size_t)(row + h * 8) * NDIM + col;
                if (Ch) {
                    __half2 hv = __floats2half2_rn(vx, vy);
                    *reinterpret_cast<__half2*>(Ch + off) = hv;
                } else {
                    *reinterpret_cast<float2*>(Cf + off) = make_float2(vx, vy);
                }
            }
        }
    }
}

extern "C" void kernel_launch(void* const* d_in, const int* in_sizes, int n_in,
                              void* d_out, int out_size) {
    const float* x   = (const float*)d_in[0];
    const int*   hi  = (const int*)d_in[1];
    const float* fc1 = (const float*)d_in[2];
    const float* fc2 = (const float*)d_in[3];
    float*       out = (float*)d_out;

    __half *xh, *f1h, *f2h, *hh;
    cudaGetSymbolAddress((void**)&xh,  g_xh);
    cudaGetSymbolAddress((void**)&f1h, g_f1h);
    cudaGetSymbolAddress((void**)&f2h, g_f2h);
    cudaGetSymbolAddress((void**)&hh,  g_hh);

    cudaFuncSetAttribute(gemm_f16_kernel<INF, HIDF, F1ROW, true>,
                         cudaFuncAttributeMaxDynamicSharedMemorySize, SMEM_BYTES);
    cudaFuncSetAttribute(gemm_f16_kernel<HIDF, OUTF, F2ROW, false>,
                         cudaFuncAttributeMaxDynamicSharedMemorySize, SMEM_BYTES);

    prep_kernel<<<296, 256>>>(hi, x, fc1, fc2);

    // GEMM1: h(fp16) = gelu(x @ W1 + b1)
    gemm_f16_kernel<INF, HIDF, F1ROW, true>
        <<<dim3(HIDF / 128, TT / 128, BB), 256, SMEM_BYTES>>>(xh, f1h, fc1, hh, nullptr);

    // GEMM2: out(fp32) = h @ W2 + b2
    gemm_f16_kernel<HIDF, OUTF, F2ROW, false>
        <<<dim3(OUTF / 128, TT / 128, BB), 256, SMEM_BYTES>>>(hh, f2h, fc2, nullptr, out);
}

// round 5
// speedup vs baseline: 4.6134x; 1.1013x over previous
#include <cuda_runtime.h>
#include <cuda_fp16.h>
#include <math.h>
#include <cstdint>

#define BB   64
#define TT   256
#define INF  512
#define HIDF 1024
#define OUTF 256
#define NDOM 20

#define F1ROW (INF * HIDF + HIDF)     // fp32 table row stride (elements)
#define F2ROW (HIDF * OUTF + OUTF)

// fp16 scratch (converted once per launch by prep kernel)
__device__ __align__(16) __half g_xh[BB * TT * INF];
__device__ __align__(16) __half g_f1h[NDOM * F1ROW];
__device__ __align__(16) __half g_f2h[NDOM * F2ROW];
__device__ __align__(16) __half g_hh[BB * TT * HIDF];   // h = gelu(x@W1+b1)
__device__ int g_dom[BB];

// ---------------------------------------------------------------------------
__device__ __forceinline__ uint32_t smem_to_u32(const void* p) {
    uint32_t a;
    asm("{ .reg .u64 t; cvta.to.shared.u64 t, %1; cvt.u32.u64 %0, t; }"
        : "=r"(a) : "l"(p));
    return a;
}
#define CP_ASYNC16(dst_u32, src_ptr) \
    asm volatile("cp.async.cg.shared.global [%0], [%1], 16;" \
                 :: "r"(dst_u32), "l"(src_ptr) : "memory")
#define CP_ASYNC_COMMIT() asm volatile("cp.async.commit_group;" ::: "memory")
#define CP_ASYNC_WAIT1()  asm volatile("cp.async.wait_group 1;" ::: "memory")
#define CP_ASYNC_WAIT0()  asm volatile("cp.async.wait_group 0;" ::: "memory")

#define LDSM_X4(r0, r1, r2, r3, addr) \
    asm volatile("ldmatrix.sync.aligned.m8n8.x4.shared.b16 {%0,%1,%2,%3}, [%4];" \
                 : "=r"(r0), "=r"(r1), "=r"(r2), "=r"(r3) : "r"(addr))
#define LDSM_X4_T(r0, r1, r2, r3, addr) \
    asm volatile("ldmatrix.sync.aligned.m8n8.x4.trans.shared.b16 {%0,%1,%2,%3}, [%4];" \
                 : "=r"(r0), "=r"(r1), "=r"(r2), "=r"(r3) : "r"(addr))

__device__ __forceinline__ void mma_f16(float* c, const uint32_t* a, const uint32_t* b) {
    asm volatile(
        "mma.sync.aligned.m16n8k16.row.col.f32.f16.f16.f32 "
        "{%0,%1,%2,%3}, {%4,%5,%6,%7}, {%8,%9}, {%0,%1,%2,%3};"
        : "+f"(c[0]), "+f"(c[1]), "+f"(c[2]), "+f"(c[3])
        : "r"(a[0]), "r"(a[1]), "r"(a[2]), "r"(a[3]), "r"(b[0]), "r"(b[1]));
}

__device__ __forceinline__ float gelu_erf(float v) {
    return 0.5f * v * (1.0f + erff(v * 0.70710678118654752f));
}

// ---------------------------------------------------------------------------
// Prep: domain decode (int64-vs-int32 robust) + fp32->fp16 converts.
// Large grid for MLP (round-4 ncu: 56% HBM at occ 23% = latency-bound).
// ---------------------------------------------------------------------------
__device__ __forceinline__ void cvt_range(const float* __restrict__ src,
                                          __half* __restrict__ dst,
                                          int n4, int gtid, int gstride) {
    for (int i = gtid; i < n4; i += gstride) {
        float4 v = *reinterpret_cast<const float4*>(src + (size_t)i * 4);
        __half2 h0 = __floats2half2_rn(v.x, v.y);
        __half2 h1 = __floats2half2_rn(v.z, v.w);
        uint2 pk = make_uint2(*(uint32_t*)&h0, *(uint32_t*)&h1);
        *reinterpret_cast<uint2*>(dst + (size_t)i * 4) = pk;
    }
}

__global__ void prep_kernel(const int* __restrict__ hi,
                            const float* __restrict__ x,
                            const float* __restrict__ fc1,
                            const float* __restrict__ fc2) {
    if (blockIdx.x == 0) {
        __shared__ int s_is64;
        int t = threadIdx.x;
        if (t == 0) s_is64 = 1;
        __syncthreads();
        if (t < 64 && hi[2 * t + 1] != 0) s_is64 = 0;
        __syncthreads();
        if (t < 64) g_dom[t] = s_is64 ? hi[4 * t] : hi[2 * t];
    }
    int gtid = blockIdx.x * blockDim.x + threadIdx.x;
    int gstride = gridDim.x * blockDim.x;
    cvt_range(x,   g_xh,  (BB * TT * INF) / 4, gtid, gstride);
    cvt_range(fc1, g_f1h, (NDOM * F1ROW) / 4,  gtid, gstride);
    cvt_range(fc2, g_f2h, (NDOM * F2ROW) / 4,  gtid, gstride);
}

// ---------------------------------------------------------------------------
// Batched fp16 GEMM: C[b] = act[b] @ W_dom (+fp32 bias, opt GELU)
// CTA tile 128x128x32, 8 warps (2M x 4N), warp tile 64x32, m16n8k16 mma.
// THREE-stage cp.async pipeline (wait_group 1); ldmatrix fragment loads.
// ---------------------------------------------------------------------------
#define AST 40     // A smem row stride (halfs): banks 20r%32 distinct
#define BST 136    // B smem row stride (halfs): banks 4k%32 distinct
#define AELEM (128 * AST)
#define BELEM (32 * BST)
#define NSTAGE 3
#define SMEM_BYTES ((NSTAGE * AELEM + NSTAGE * BELEM) * 2)

template <int KDIM, int NDIM, int WROW, bool GELU>
__global__ void __launch_bounds__(256, 2)
gemm_f16_kernel(const __half* __restrict__ Act,    // [BB][TT][KDIM] halfs
                const __half* __restrict__ Wtab,   // [NDOM][WROW] halfs
                const float* __restrict__ Ftab,    // fp32 table (for bias)
                __half* __restrict__ Ch,           // fp16 out (or null)
                float* __restrict__ Cf)            // fp32 out (or null)
{
    extern __shared__ __half smem[];
    __half* As = smem;
    __half* Bs = smem + NSTAGE * AELEM;
    const uint32_t as_u32 = smem_to_u32(As);
    const uint32_t bs_u32 = smem_to_u32(Bs);

    const int t    = threadIdx.x;
    const int lid  = t & 31;
    const int wid  = t >> 5;
    const int wm   = wid & 1;
    const int wn   = wid >> 1;
    const int gid  = lid >> 2;
    const int tid4 = lid & 3;

    const int b   = blockIdx.z;
    const int n0  = blockIdx.x * 128;
    const int m0  = blockIdx.y * 128;
    const int dom = g_dom[b];

    const __half* Ag   = Act + (size_t)b * TT * KDIM + (size_t)m0 * KDIM;
    const __half* Wg   = Wtab + (size_t)dom * WROW;
    const float*  bias = Ftab + (size_t)dom * WROW + (size_t)KDIM * NDIM;

    // per-thread staging coords (hoisted)
    const int s_ar  = t >> 2,        s_akc = t & 3;      // A: rows 0..63 (+64 on it=1)
    const int s_br  = t >> 4,        s_bnc = t & 15;     // B: rows 0..15 (+16 on it=1)

    float acc[4][4][4];
#pragma unroll
    for (int i = 0; i < 4; i++)
#pragma unroll
        for (int j = 0; j < 4; j++)
#pragma unroll
            for (int q = 0; q < 4; q++) acc[i][j][q] = 0.0f;

    constexpr int NKT = KDIM / 32;

    // per-thread ldmatrix source offsets (halfs)
    const int a_row   = wm * 64 + (lid & 15);
    const int a_col   = (lid >> 4) * 8;
    const int b_krow  = lid & 15;
    const int b_ncol0 = wn * 32 + (lid >> 4) * 8;

    auto stage_tile = [&](int kt, int buf) {
        const int k0 = kt * 32;
        const uint32_t ab = as_u32 + (uint32_t)(buf * AELEM) * 2;
        const uint32_t bb = bs_u32 + (uint32_t)(buf * BELEM) * 2;
#pragma unroll
        for (int it = 0; it < 2; it++) {
            int ar = s_ar + it * 64;
            CP_ASYNC16(ab + (uint32_t)(ar * AST + s_akc * 8) * 2,
                       Ag + (size_t)ar * KDIM + k0 + s_akc * 8);
            int br = s_br + it * 16;
            CP_ASYNC16(bb + (uint32_t)(br * BST + s_bnc * 8) * 2,
                       Wg + (size_t)(k0 + br) * NDIM + n0 + s_bnc * 8);
        }
        CP_ASYNC_COMMIT();
    };

    // ---- prologue: stage tiles 0 and 1
    stage_tile(0, 0);
    stage_tile(1, 1);

    int buf = 0, nbuf = 2;  // nbuf = buffer index for tile kt+2
    for (int kt = 0; kt < NKT; kt++) {
        CP_ASYNC_WAIT1();     // tile kt complete (kt+1 may still be in flight)
        __syncthreads();

        if (kt + 2 < NKT) {
            stage_tile(kt + 2, nbuf);
        } else {
            CP_ASYNC_COMMIT();  // keep group count in lockstep for WAIT1 semantics
        }

        const uint32_t ab = as_u32 + (uint32_t)(buf * AELEM) * 2;
        const uint32_t bb = bs_u32 + (uint32_t)(buf * BELEM) * 2;
#pragma unroll
        for (int ks = 0; ks < 2; ks++) {
            uint32_t af[4][4];
#pragma unroll
            for (int i = 0; i < 4; i++) {
                uint32_t addr = ab + (uint32_t)((a_row + i * 16) * AST + ks * 16 + a_col) * 2;
                LDSM_X4(af[i][0], af[i][1], af[i][2], af[i][3], addr);
            }
            uint32_t bf[4][2];
#pragma unroll
            for (int jp = 0; jp < 2; jp++) {
                uint32_t addr = bb + (uint32_t)((ks * 16 + b_krow) * BST + b_ncol0 + jp * 16) * 2;
                LDSM_X4_T(bf[jp * 2][0], bf[jp * 2][1], bf[jp * 2 + 1][0], bf[jp * 2 + 1][1], addr);
            }
#pragma unroll
            for (int i = 0; i < 4; i++)
#pragma unroll
                for (int j = 0; j < 4; j++)
                    mma_f16(acc[i][j], af[i], bf[j]);
        }
        buf  = (buf == NSTAGE - 1) ? 0 : buf + 1;
        nbuf = (nbuf == NSTAGE - 1) ? 0 : nbuf + 1;
    }

    // ---- epilogue: fp32 bias (+GELU); store fp16 or fp32
#pragma unroll
    for (int i = 0; i < 4; i++) {
#pragma unroll
        for (int j = 0; j < 4; j++) {
            int row = m0 + wm * 64 + i * 16 + gid;
            int col = n0 + wn * 32 + j * 8 + tid4 * 2;
            float b0 = __ldg(bias + col), b1 = __ldg(bias + col + 1);
#pragma unroll
            for (int h = 0; h < 2; h++) {
                float vx = acc[i][j][h * 2 + 0] + b0;
                float vy = acc[i][j][h * 2 + 1] + b1;
                if (GELU) { vx = gelu_erf(vx); vy = gelu_erf(vy); }
                size_t off = (size_t)b * TT * NDIM + (size_t)(row + h * 8) * NDIM + col;
                if (Ch) {
                    __half2 hv = __floats2half2_rn(vx, vy);
                    *reinterpret_cast<__half2*>(Ch + off) = hv;
                } else {
                    *reinterpret_cast<float2*>(Cf + off) = make_float2(vx, vy);
                }
            }
        }
    }
}

extern "C" void kernel_launch(void* const* d_in, const int* in_sizes, int n_in,
                              void* d_out, int out_size) {
    const float* x   = (const float*)d_in[0];
    const int*   hi  = (const int*)d_in[1];
    const float* fc1 = (const float*)d_in[2];
    const float* fc2 = (const float*)d_in[3];
    float*       out = (float*)d_out;

    __half *xh, *f1h, *f2h, *hh;
    cudaGetSymbolAddress((void**)&xh,  g_xh);
    cudaGetSymbolAddress((void**)&f1h, g_f1h);
    cudaGetSymbolAddress((void**)&f2h, g_f2h);
    cudaGetSymbolAddress((void**)&hh,  g_hh);

    cudaFuncSetAttribute(gemm_f16_kernel<INF, HIDF, F1ROW, true>,
                         cudaFuncAttributeMaxDynamicSharedMemorySize, SMEM_BYTES);
    cudaFuncSetAttribute(gemm_f16_kernel<HIDF, OUTF, F2ROW, false>,
                         cudaFuncAttributeMaxDynamicSharedMemorySize, SMEM_BYTES);

    prep_kernel<<<1184, 256>>>(hi, x, fc1, fc2);

    // GEMM1: h(fp16) = gelu(x @ W1 + b1)
    gemm_f16_kernel<INF, HIDF, F1ROW, true>
        <<<dim3(HIDF / 128, TT / 128, BB), 256, SMEM_BYTES>>>(xh, f1h, fc1, hh, nullptr);

    // GEMM2: out(fp32) = h @ W2 + b2
    gemm_f16_kernel<HIDF, OUTF, F2ROW, false>
        <<<dim3(OUTF / 128, TT / 128, BB), 256, SMEM_BYTES>>>(hh, f2h, fc2, nullptr, out);
}

// round 7
// speedup vs baseline: 4.7021x; 1.0192x over previous
#include <cuda_runtime.h>
#include <cuda_fp16.h>
#include <math.h>
#include <cstdint>

#define BB   64
#define TT   256
#define INF  512
#define HIDF 1024
#define OUTF 256
#define NDOM 20

#define F1ROW (INF * HIDF + HIDF)
#define F2ROW (HIDF * OUTF + OUTF)
#define GRIDP 296          // persistent grid: 2 CTAs x 148 SMs

__device__ __align__(16) __half g_xh[BB * TT * INF];
__device__ __align__(16) __half g_f1h[NDOM * F1ROW];
__device__ __align__(16) __half g_f2h[NDOM * F2ROW];
__device__ __align__(16) __half g_hh[BB * TT * HIDF];
__device__ int g_dom[BB];

// ---------------------------------------------------------------------------
__device__ __forceinline__ uint32_t smem_to_u32(const void* p) {
    uint32_t a;
    asm("{ .reg .u64 t; cvta.to.shared.u64 t, %1; cvt.u32.u64 %0, t; }"
        : "=r"(a) : "l"(p));
    return a;
}
#define CP_ASYNC16(dst_u32, src_ptr) \
    asm volatile("cp.async.cg.shared.global [%0], [%1], 16;" \
                 :: "r"(dst_u32), "l"(src_ptr) : "memory")
#define CP_ASYNC_COMMIT() asm volatile("cp.async.commit_group;" ::: "memory")
#define CP_ASYNC_WAIT1()  asm volatile("cp.async.wait_group 1;" ::: "memory")

#define LDSM_X4(r0, r1, r2, r3, addr) \
    asm volatile("ldmatrix.sync.aligned.m8n8.x4.shared.b16 {%0,%1,%2,%3}, [%4];" \
                 : "=r"(r0), "=r"(r1), "=r"(r2), "=r"(r3) : "r"(addr))
#define LDSM_X4_T(r0, r1, r2, r3, addr) \
    asm volatile("ldmatrix.sync.aligned.m8n8.x4.trans.shared.b16 {%0,%1,%2,%3}, [%4];" \
                 : "=r"(r0), "=r"(r1), "=r"(r2), "=r"(r3) : "r"(addr))

__device__ __forceinline__ void mma_f16(float* c, const uint32_t* a, const uint32_t* b) {
    asm volatile(
        "mma.sync.aligned.m16n8k16.row.col.f32.f16.f16.f32 "
        "{%0,%1,%2,%3}, {%4,%5,%6,%7}, {%8,%9}, {%0,%1,%2,%3};"
        : "+f"(c[0]), "+f"(c[1]), "+f"(c[2]), "+f"(c[3])
        : "r"(a[0]), "r"(a[1]), "r"(a[2]), "r"(a[3]), "r"(b[0]), "r"(b[1]));
}

__device__ __forceinline__ float gelu_erf(float v) {
    return 0.5f * v * (1.0f + erff(v * 0.70710678118654752f));
}

__host__ __device__ constexpr int ilog2c(int v) { int l = 0; while (v >>= 1) l++; return l; }

// ---------------------------------------------------------------------------
// Prep: domain decode (int64-vs-int32 robust) + fp32->fp16 converts
// ---------------------------------------------------------------------------
__device__ __forceinline__ void cvt_range(const float* __restrict__ src,
                                          __half* __restrict__ dst,
                                          int n4, int gtid, int gstride) {
    for (int i = gtid; i < n4; i += gstride) {
        float4 v = *reinterpret_cast<const float4*>(src + (size_t)i * 4);
        __half2 h0 = __floats2half2_rn(v.x, v.y);
        __half2 h1 = __floats2half2_rn(v.z, v.w);
        uint2 pk = make_uint2(*(uint32_t*)&h0, *(uint32_t*)&h1);
        *reinterpret_cast<uint2*>(dst + (size_t)i * 4) = pk;
    }
}

__global__ void prep_kernel(const int* __restrict__ hi,
                            const float* __restrict__ x,
                            const float* __restrict__ fc1,
                            const float* __restrict__ fc2) {
    if (blockIdx.x == 0) {
        __shared__ int s_is64;
        int t = threadIdx.x;
        if (t == 0) s_is64 = 1;
        __syncthreads();
        if (t < 64 && hi[2 * t + 1] != 0) s_is64 = 0;
        __syncthreads();
        if (t < 64) g_dom[t] = s_is64 ? hi[4 * t] : hi[2 * t];
    }
    int gtid = blockIdx.x * blockDim.x + threadIdx.x;
    int gstride = gridDim.x * blockDim.x;
    cvt_range(x,   g_xh,  (BB * TT * INF) / 4, gtid, gstride);
    cvt_range(fc1, g_f1h, (NDOM * F1ROW) / 4,  gtid, gstride);
    cvt_range(fc2, g_f2h, (NDOM * F2ROW) / 4,  gtid, gstride);
}

// ---------------------------------------------------------------------------
// Persistent batched fp16 GEMM. Each CTA loops tiles ti = bid, bid+GRIDP, ...
// cp.async pipeline is FLATTENED across the CTA's whole k-tile sequence:
// buffers cycle mod 3 continuously; staging runs 2 k-tiles ahead, so the
// next tile's loads overlap this tile's epilogue (bias+GELU+stores).
// CTA tile 128x128x32, 8 warps (2M x 4N), m16n8k16.
// ---------------------------------------------------------------------------
#define AST 40
#define BST 136
#define AELEM (128 * AST)
#define BELEM (32 * BST)
#define NSTAGE 3
#define SMEM_BYTES ((NSTAGE * AELEM + NSTAGE * BELEM) * 2)

template <int KDIM, int NDIM, int WROW, bool GELU>
__global__ void __launch_bounds__(256, 2)
gemm_f16_persist(const __half* __restrict__ Act,   // [BB][TT][KDIM]
                 const __half* __restrict__ Wtab,  // [NDOM][WROW]
                 const float* __restrict__ Ftab,   // fp32 table (bias)
                 __half* __restrict__ Ch,          // fp16 out (or null)
                 float* __restrict__ Cf)           // fp32 out (or null)
{
    constexpr int NKT    = KDIM / 32;
    constexpr int LOGNKT = ilog2c(NKT);
    constexpr int NTN    = NDIM / 128;
    constexpr int NTM    = TT / 128;
    constexpr int NTILE  = NTN * NTM;
    constexpr int LOGNTI = ilog2c(NTILE);
    constexpr int LOGNTN = ilog2c(NTN);
    constexpr int NT     = NTILE * BB;

    extern __shared__ __half smem[];
    const uint32_t as_u32 = smem_to_u32(smem);
    const uint32_t bs_u32 = as_u32 + NSTAGE * AELEM * 2;

    const int t    = threadIdx.x;
    const int lid  = t & 31;
    const int wid  = t >> 5;
    const int wm   = wid & 1;
    const int wn   = wid >> 1;
    const int gid  = lid >> 2;
    const int tid4 = lid & 3;
    const int bid  = blockIdx.x;

    // number of tiles for this CTA; S = total flattened k-tile steps
    const int tcount = (bid < NT) ? ((NT - bid + GRIDP - 1) / GRIDP) : 0;
    const int S = tcount << LOGNKT;
    if (S == 0) return;

    // staging coords
    const int s_ar = t >> 2, s_akc = t & 3;
    const int s_br = t >> 4, s_bnc = t & 15;
    // ldmatrix coords
    const int a_row   = wm * 64 + (lid & 15);
    const int a_col   = (lid >> 4) * 8;
    const int b_krow  = lid & 15;
    const int b_ncol0 = wn * 32 + (lid >> 4) * 8;

    auto stage = [&](int s, int buf) {
        const int tl = s >> LOGNKT;
        const int kt = s & (NKT - 1);
        const int ti = bid + tl * GRIDP;
        const int b  = ti >> LOGNTI;
        const int r  = ti & (NTILE - 1);
        const int m0 = (r >> LOGNTN) * 128;
        const int n0 = (r & (NTN - 1)) * 128;
        const __half* Ag = Act + ((size_t)b * TT + m0) * KDIM + kt * 32;
        const __half* Wg = Wtab + (size_t)__ldg(&g_dom[b]) * WROW
                               + (size_t)(kt * 32) * NDIM + n0;
        const uint32_t ab = as_u32 + (uint32_t)(buf * AELEM) * 2;
        const uint32_t bb = bs_u32 + (uint32_t)(buf * BELEM) * 2;
#pragma unroll
        for (int it = 0; it < 2; it++) {
            int ar = s_ar + it * 64;
            CP_ASYNC16(ab + (uint32_t)(ar * AST + s_akc * 8) * 2,
                       Ag + (size_t)ar * KDIM + s_akc * 8);
            int br = s_br + it * 16;
            CP_ASYNC16(bb + (uint32_t)(br * BST + s_bnc * 8) * 2,
                       Wg + (size_t)br * NDIM + s_bnc * 8);
        }
        CP_ASYNC_COMMIT();
    };

    float acc[4][4][4];
#pragma unroll
    for (int i = 0; i < 4; i++)
#pragma unroll
        for (int j = 0; j < 4; j++)
#pragma unroll
            for (int q = 0; q < 4; q++) acc[i][j][q] = 0.0f;

    stage(0, 0);
    if (S > 1) stage(1, 1); else CP_ASYNC_COMMIT();

    int buf = 0;
    for (int s = 0; s < S; s++) {
        CP_ASYNC_WAIT1();
        __syncthreads();

        if (s + 2 < S) {
            stage(s + 2, (buf == 0) ? 2 : buf - 1);   // buf+2 mod 3
        } else {
            CP_ASYNC_COMMIT();
        }

        const uint32_t ab = as_u32 + (uint32_t)(buf * AELEM) * 2;
        const uint32_t bb = bs_u32 + (uint32_t)(buf * BELEM) * 2;
#pragma unroll
        for (int ks = 0; ks < 2; ks++) {
            uint32_t af[4][4];
#pragma unroll
            for (int i = 0; i < 4; i++) {
                uint32_t addr = ab + (uint32_t)((a_row + i * 16) * AST + ks * 16 + a_col) * 2;
                LDSM_X4(af[i][0], af[i][1], af[i][2], af[i][3], addr);
            }
            uint32_t bf[4][2];
#pragma unroll
            for (int jp = 0; jp < 2; jp++) {
                uint32_t addr = bb + (uint32_t)((ks * 16 + b_krow) * BST + b_ncol0 + jp * 16) * 2;
                LDSM_X4_T(bf[jp * 2][0], bf[jp * 2][1], bf[jp * 2 + 1][0], bf[jp * 2 + 1][1], addr);
            }
#pragma unroll
            for (int i = 0; i < 4; i++)
#pragma unroll
                for (int j = 0; j < 4; j++)
                    mma_f16(acc[i][j], af[i], bf[j]);
        }
        buf = (buf == NSTAGE - 1) ? 0 : buf + 1;

        // ---- tile boundary: epilogue (overlaps already-issued next-tile loads)
        if ((s & (NKT - 1)) == NKT - 1) {
            const int ti = bid + (s >> LOGNKT) * GRIDP;
            const int b  = ti >> LOGNTI;
            const int r  = ti & (NTILE - 1);
            const int m0 = (r >> LOGNTN) * 128;
            const int n0 = (r & (NTN - 1)) * 128;
            const float* bias = Ftab + (size_t)__ldg(&g_dom[b]) * WROW
                                     + (size_t)KDIM * NDIM;
#pragma unroll
            for (int i = 0; i < 4; i++) {
#pragma unroll
                for (int j = 0; j < 4; j++) {
                    int row = m0 + wm * 64 + i * 16 + gid;
                    int col = n0 + wn * 32 + j * 8 + tid4 * 2;
                    float b0 = __ldg(bias + col), b1 = __ldg(bias + col + 1);
#pragma unroll
                    for (int h = 0; h < 2; h++) {
                        float vx = acc[i][j][h * 2 + 0] + b0;
                        float vy = acc[i][j][h * 2 + 1] + b1;
                        if (GELU) { vx = gelu_erf(vx); vy = gelu_erf(vy); }
                        size_t off = (size_t)b * TT * NDIM
                                   + (size_t)(row + h * 8) * NDIM + col;
                        if (Ch) {
                            __half2 hv = __floats2half2_rn(vx, vy);
                            *reinterpret_cast<__half2*>(Ch + off) = hv;
                        } else {
                            *reinterpret_cast<float2*>(Cf + off) = make_float2(vx, vy);
                        }
                        acc[i][j][h * 2 + 0] = 0.0f;
                        acc[i][j][h * 2 + 1] = 0.0f;
                    }
                }
            }
        }
    }
}

extern "C" void kernel_launch(void* const* d_in, const int* in_sizes, int n_in,
                              void* d_out, int out_size) {
    const float* x   = (const float*)d_in[0];
    const int*   hi  = (const int*)d_in[1];
    const float* fc1 = (const float*)d_in[2];
    const float* fc2 = (const float*)d_in[3];
    float*       out = (float*)d_out;

    __half *xh, *f1h, *f2h, *hh;
    cudaGetSymbolAddress((void**)&xh,  g_xh);
    cudaGetSymbolAddress((void**)&f1h, g_f1h);
    cudaGetSymbolAddress((void**)&f2h, g_f2h);
    cudaGetSymbolAddress((void**)&hh,  g_hh);

    cudaFuncSetAttribute(gemm_f16_persist<INF, HIDF, F1ROW, true>,
                         cudaFuncAttributeMaxDynamicSharedMemorySize, SMEM_BYTES);
    cudaFuncSetAttribute(gemm_f16_persist<HIDF, OUTF, F2ROW, false>,
                         cudaFuncAttributeMaxDynamicSharedMemorySize, SMEM_BYTES);

    prep_kernel<<<1184, 256>>>(hi, x, fc1, fc2);

    // GEMM1: h(fp16) = gelu(x @ W1 + b1)   (1024 tiles over 296 persistent CTAs)
    gemm_f16_persist<INF, HIDF, F1ROW, true>
        <<<GRIDP, 256, SMEM_BYTES>>>(xh, f1h, fc1, hh, nullptr);

    // GEMM2: out(fp32) = h @ W2 + b2       (256 tiles)
    gemm_f16_persist<HIDF, OUTF, F2ROW, false>
        <<<GRIDP, 256, SMEM_BYTES>>>(hh, f2h, fc2, nullptr, out);
}